// round 8
// baseline (speedup 1.0000x reference)
#include <cuda_runtime.h>
#include <cuda_bf16.h>
#include <cstdint>

#define BB 2
#define LL 2048
#define DM 1024
#define NH 16
#define MM (BB*LL)

// ---------------- device scratch (bf16 hi/lo pairs) -------------------------
__device__ __align__(16) __nv_bfloat16 g_xh[MM*DM], g_xl[MM*DM];
__device__ __align__(16) __nv_bfloat16 g_wh[4][DM*DM], g_wl[4][DM*DM];
__device__ __align__(16) __nv_bfloat16 g_Qh[MM*DM], g_Ql[MM*DM];   // [bh][l][64], pre-scaled log2e/8
__device__ __align__(16) __nv_bfloat16 g_Kh[MM*DM], g_Kl[MM*DM];   // [bh][l][64]
__device__ __align__(16) __nv_bfloat16 g_Vh[MM*DM], g_Vl[MM*DM];   // transposed [bh][d][l]
__device__ __align__(16) __nv_bfloat16 g_Oh[MM*DM], g_Ol[MM*DM];   // [b][l][1024]

// ---------------- mma / ldmatrix / cp.async helpers -------------------------
__device__ __forceinline__ void mma16816(float* c, const uint32_t* a, const uint32_t* b){
    asm volatile("mma.sync.aligned.m16n8k16.row.col.f32.bf16.bf16.f32 "
        "{%0,%1,%2,%3}, {%4,%5,%6,%7}, {%8,%9}, {%0,%1,%2,%3};"
        : "+f"(c[0]), "+f"(c[1]), "+f"(c[2]), "+f"(c[3])
        : "r"(a[0]), "r"(a[1]), "r"(a[2]), "r"(a[3]), "r"(b[0]), "r"(b[1]));
}
__device__ __forceinline__ uint32_t smem_u32(const void* p){
    uint32_t a;
    asm("{ .reg .u64 t; cvta.to.shared.u64 t, %1; cvt.u32.u64 %0, t; }" : "=r"(a) : "l"(p));
    return a;
}
__device__ __forceinline__ void ldmA(uint32_t* a, const __nv_bfloat16* s, int S, int m0, int k0, int lane){
    const __nv_bfloat16* p = s + (size_t)(m0 + (lane & 15)) * S + k0 + ((lane >> 4) << 3);
    asm volatile("ldmatrix.sync.aligned.m8n8.x4.shared.b16 {%0,%1,%2,%3}, [%4];"
        : "=r"(a[0]), "=r"(a[1]), "=r"(a[2]), "=r"(a[3]) : "r"(smem_u32(p)));
}
__device__ __forceinline__ void ldmB(uint32_t* b, const __nv_bfloat16* s, int S, int n0, int k0, int lane){
    const __nv_bfloat16* p = s + (size_t)(n0 + (lane & 7)) * S + k0 + (((lane >> 3) & 1) << 3);
    asm volatile("ldmatrix.sync.aligned.m8n8.x2.shared.b16 {%0,%1}, [%2];"
        : "=r"(b[0]), "=r"(b[1]) : "r"(smem_u32(p)));
}
__device__ __forceinline__ void cp16(const __nv_bfloat16* dst, const __nv_bfloat16* src){
    asm volatile("cp.async.ca.shared.global [%0], [%1], 16;" :: "r"(smem_u32(dst)), "l"(src));
}
#define CP_COMMIT() asm volatile("cp.async.commit_group;" ::: "memory")
__device__ __forceinline__ void split_bf(float v, __nv_bfloat16& h, __nv_bfloat16& l){
    h = __float2bfloat16(v);
    l = __float2bfloat16(v - __bfloat162float(h));
}
__device__ __forceinline__ float fex2(float x){
    float y; asm("ex2.approx.f32 %0, %1;" : "=f"(y) : "f"(x)); return y;
}

// ============================================================================
// fp32 -> hi/lo bf16, vectorized, all tensors in one launch
// ============================================================================
__global__ __launch_bounds__(256) void cvt_all_kernel(
    const float* __restrict__ x,  const float* __restrict__ wq,
    const float* __restrict__ wk, const float* __restrict__ wv,
    const float* __restrict__ wo)
{
    size_t i4 = ((size_t)blockIdx.x * 256 + threadIdx.x) * 4;
    const float* s; __nv_bfloat16 *dh, *dl; size_t off;
    if (i4 < (size_t)MM * DM) {
        s = x; dh = g_xh; dl = g_xl; off = i4;
    } else {
        size_t j = i4 - (size_t)MM * DM;
        int t = (int)(j >> 20);
        off = j & ((1u << 20) - 1);
        s = (t == 0) ? wq : (t == 1) ? wk : (t == 2) ? wv : wo;
        dh = g_wh[t]; dl = g_wl[t];
    }
    float4 v = *(const float4*)(s + off);
    __nv_bfloat16 h0,l0,h1,l1,h2,l2,h3,l3;
    split_bf(v.x,h0,l0); split_bf(v.y,h1,l1); split_bf(v.z,h2,l2); split_bf(v.w,h3,l3);
    __nv_bfloat162 hh[2] = {__halves2bfloat162(h0,h1), __halves2bfloat162(h2,h3)};
    __nv_bfloat162 ll[2] = {__halves2bfloat162(l0,l1), __halves2bfloat162(l2,l3)};
    *(uint2*)(dh + off) = *(uint2*)hh;
    *(uint2*)(dl + off) = *(uint2*)ll;
}

// ============================================================================
// projection GEMM, cp.async double-buffered, ldmatrix, 2 CTAs/SM.
// ============================================================================
#define SA 40
#define STG (4*128*SA)
__global__ __launch_bounds__(256, 2) void proj_kernel(
    const float* __restrict__ b0, const float* __restrict__ b1,
    const float* __restrict__ b2, float* __restrict__ fout, int mode_arg)
{
    extern __shared__ char smraw[];
    __nv_bfloat16* S = (__nv_bfloat16*)smraw;
    __shared__ float s_bias[128];

    const int mode = (mode_arg < 0) ? (int)blockIdx.z : mode_arg;
    const float* bias = (mode == 1) ? b1 : (mode == 2) ? b2 : b0;
    const __nv_bfloat16* gAh = (mode < 3) ? g_xh : g_Oh;
    const __nv_bfloat16* gAl = (mode < 3) ? g_xl : g_Ol;
    const __nv_bfloat16* gBh = g_wh[mode];
    const __nv_bfloat16* gBl = g_wl[mode];

    const int bm = blockIdx.y * 128, bn = blockIdx.x * 128;
    const int tid = threadIdx.x, w = tid >> 5, lane = tid & 31;
    const int wm = w >> 2, wn = w & 3;
    if (tid < 128) s_bias[tid] = bias[bn + tid];

    float C[4][4][4];
    #pragma unroll
    for (int i = 0; i < 4; i++)
        #pragma unroll
        for (int j = 0; j < 4; j++)
            #pragma unroll
            for (int q = 0; q < 4; q++) C[i][j][q] = 0.f;

    #pragma unroll
    for (int i = tid; i < 2048; i += 256) {
        int t = i >> 9, e = i & 511, r = e >> 2, c4 = e & 3;
        const __nv_bfloat16* src = (t==0)?gAh:(t==1)?gAl:(t==2)?gBh:gBl;
        int rowbase = (t < 2) ? bm : bn;
        cp16(S + t * 5120 + r * SA + c4 * 8, src + (size_t)(rowbase + r) * DM + c4 * 8);
    }
    CP_COMMIT();

    for (int it = 0; it < 32; it++) {
        const int cur = it & 1;
        if (it + 1 < 32) {
            const int k0n = (it + 1) * 32, nxt = cur ^ 1;
            #pragma unroll
            for (int i = tid; i < 2048; i += 256) {
                int t = i >> 9, e = i & 511, r = e >> 2, c4 = e & 3;
                const __nv_bfloat16* src = (t==0)?gAh:(t==1)?gAl:(t==2)?gBh:gBl;
                int rowbase = (t < 2) ? bm : bn;
                cp16(S + nxt * STG + t * 5120 + r * SA + c4 * 8,
                     src + (size_t)(rowbase + r) * DM + k0n + c4 * 8);
            }
            CP_COMMIT();
            asm volatile("cp.async.wait_group 1;" ::: "memory");
        } else {
            asm volatile("cp.async.wait_group 0;" ::: "memory");
        }
        __syncthreads();

        const __nv_bfloat16 *Ah = S + cur * STG, *Al = Ah + 5120,
                            *Bh = Ah + 10240,     *Bl = Ah + 15360;
        #pragma unroll
        for (int ks = 0; ks < 2; ks++) {
            uint32_t fbh[4][2], fbl[4][2];
            #pragma unroll
            for (int nt = 0; nt < 4; nt++) {
                ldmB(fbh[nt], Bh, SA, wn * 32 + nt * 8, ks * 16, lane);
                ldmB(fbl[nt], Bl, SA, wn * 32 + nt * 8, ks * 16, lane);
            }
            #pragma unroll
            for (int mt = 0; mt < 4; mt++) {
                uint32_t fah[4], fal[4];
                ldmA(fah, Ah, SA, wm * 64 + mt * 16, ks * 16, lane);
                ldmA(fal, Al, SA, wm * 64 + mt * 16, ks * 16, lane);
                #pragma unroll
                for (int nt = 0; nt < 4; nt++) {
                    mma16816(C[mt][nt], fah, fbh[nt]);
                    mma16816(C[mt][nt], fah, fbl[nt]);
                    mma16816(C[mt][nt], fal, fbh[nt]);
                }
            }
        }
        __syncthreads();
    }

    const int r = lane >> 2, cq = lane & 3;
    // Q pre-scaled by log2e/8 so attention can use pure ex2
    const float scl = (mode == 0) ? 0.18033688011112042f : 1.0f;
    #pragma unroll
    for (int mt = 0; mt < 4; mt++) {
        #pragma unroll
        for (int nt = 0; nt < 4; nt++) {
            int nloc = wn * 32 + nt * 8 + 2 * cq;
            int n = bn + nloc;
            #pragma unroll
            for (int hf = 0; hf < 2; hf++) {
                int m = bm + wm * 64 + mt * 16 + r + hf * 8;
                float v0 = (C[mt][nt][hf*2+0] + s_bias[nloc])     * scl;
                float v1 = (C[mt][nt][hf*2+1] + s_bias[nloc + 1]) * scl;
                if (mode == 3) {
                    *(float2*)(fout + (size_t)m * DM + n) = make_float2(v0, v1);
                } else {
                    int bidx = m >> 11, l = m & 2047, h = n >> 6, d = n & 63;
                    __nv_bfloat16 h0,l0,h1,l1; split_bf(v0,h0,l0); split_bf(v1,h1,l1);
                    if (mode < 2) {
                        __nv_bfloat16* DH = mode == 0 ? g_Qh : g_Kh;
                        __nv_bfloat16* DL = mode == 0 ? g_Ql : g_Kl;
                        size_t idx = (((size_t)bidx * NH + h) * LL + l) * 64 + d;
                        *(__nv_bfloat162*)(DH + idx) = __halves2bfloat162(h0, h1);
                        *(__nv_bfloat162*)(DL + idx) = __halves2bfloat162(l0, l1);
                    } else {
                        size_t idx = (((size_t)bidx * NH + h) * 64 + d) * LL + l;
                        g_Vh[idx] = h0; g_Vl[idx] = l0;
                        g_Vh[idx + LL] = h1; g_Vl[idx + LL] = l1;
                    }
                }
            }
        }
    }
}

// ============================================================================
// fused attention, TWO PASS, q-tile 64, 2 CTAs/SM.
// pass1: S = Qh.Kh (1 MMA), Kh double-buffered, rowsums -> inv.
// pass2: S 3-MMA -> normalized attn + P hi/lo (ALIASED into K space after
//        S phase) -> O += (Ph+Pl).Vh + Ph.Vl.
// smem elems: Qh 0, Ql 4608 | K/P union: Kh 9216, Kl 18432 (P: Ph 9216,
// Pl 17920) | Vh 27648, Vl 36352 | total 45056 elems = 90112 B
// ============================================================================
#define SQ 72
#define SV 136
__global__ __launch_bounds__(256, 2) void attn_kernel(const int* __restrict__ mask,
                                                      float* __restrict__ attn){
    extern __shared__ char smraw[];
    __nv_bfloat16* S = (__nv_bfloat16*)smraw;
    __nv_bfloat16 *Qh = S,          *Ql = S + 4608,
                  *Kh = S + 9216,   *Kl = S + 18432,
                  *Ph = S + 9216,   *Pl = S + 17920,
                  *Vh = S + 27648,  *Vl = S + 36352;
    __shared__ float s_msk[128];
    __shared__ float s_rs[64][4];
    __shared__ float s_inv[64];

    const int bh = blockIdx.y, q0 = blockIdx.x * 64, b = bh >> 4;
    const int tid = threadIdx.x, w = tid >> 5, lane = tid & 31;
    const int wq = w >> 2, wn = w & 3;
    const int r = lane >> 2, cq = lane & 3;

    // persistent Q tile [64][64] hi/lo
    #pragma unroll
    for (int i = tid; i < 1024; i += 256) {
        int t = i >> 9, e = i & 511, rr = e >> 3, c8 = e & 7;
        const __nv_bfloat16* src = (t ? g_Ql : g_Qh) + ((size_t)bh * LL + q0) * 64;
        cp16((t ? Ql : Qh) + rr * SQ + c8 * 8, src + (size_t)rr * 64 + c8 * 8);
    }
    // prefetch pass-1 Kh stage 0
    #pragma unroll
    for (int i = tid; i < 1024; i += 256) {
        int rr = i >> 3, c8 = i & 7;
        cp16(Kh + rr * SQ + c8 * 8,
             g_Kh + (size_t)bh * LL * 64 + (size_t)rr * 64 + c8 * 8);
    }
    CP_COMMIT();

    float rs[2][2] = {{0,0},{0,0}};

    // ---------------- pass 1: rowsums (Qh.Kh only, double-buffered) --------
    for (int kt = 0; kt < 16; kt++) {
        __syncthreads();      // prev iter done with s_msk and the nxt stage
        const __nv_bfloat16* Kcur = (kt & 1) ? Kl : Kh;   // Kl slot = stage 1
        if (kt + 1 < 16) {
            __nv_bfloat16* Knxt = (kt & 1) ? Kh : Kl;
            const __nv_bfloat16* src = g_Kh + ((size_t)bh * LL + (kt + 1) * 128) * 64;
            #pragma unroll
            for (int i = tid; i < 1024; i += 256) {
                int rr = i >> 3, c8 = i & 7;
                cp16(Knxt + rr * SQ + c8 * 8, src + (size_t)rr * 64 + c8 * 8);
            }
            CP_COMMIT();
            asm volatile("cp.async.wait_group 1;" ::: "memory");
        } else {
            asm volatile("cp.async.wait_group 0;" ::: "memory");
        }
        if (tid < 128) s_msk[tid] = mask[b * LL + kt * 128 + tid] ? 1.f : 0.f;
        __syncthreads();

        float Cs[2][4][4];
        #pragma unroll
        for (int i=0;i<2;i++) for (int j=0;j<4;j++) for (int q=0;q<4;q++) Cs[i][j][q]=0.f;
        #pragma unroll
        for (int ks = 0; ks < 4; ks++) {
            uint32_t fbh[4][2];
            #pragma unroll
            for (int nt = 0; nt < 4; nt++)
                ldmB(fbh[nt], Kcur, SQ, wn * 32 + nt * 8, ks * 16, lane);
            #pragma unroll
            for (int mt = 0; mt < 2; mt++) {
                uint32_t fah[4];
                ldmA(fah, Qh, SQ, wq * 32 + mt * 16, ks * 16, lane);
                #pragma unroll
                for (int nt = 0; nt < 4; nt++)
                    mma16816(Cs[mt][nt], fah, fbh[nt]);
            }
        }
        #pragma unroll
        for (int mt = 0; mt < 2; mt++)
            #pragma unroll
            for (int nt = 0; nt < 4; nt++) {
                int col = wn * 32 + nt * 8 + 2 * cq;
                float m0 = s_msk[col], m1 = s_msk[col + 1];
                #pragma unroll
                for (int hf = 0; hf < 2; hf++)
                    rs[mt][hf] += fex2(Cs[mt][nt][hf*2+0]) * m0
                                + fex2(Cs[mt][nt][hf*2+1]) * m1;
            }
    }

    #pragma unroll
    for (int mt = 0; mt < 2; mt++)
        #pragma unroll
        for (int hf = 0; hf < 2; hf++) {
            rs[mt][hf] += __shfl_xor_sync(0xffffffffu, rs[mt][hf], 1);
            rs[mt][hf] += __shfl_xor_sync(0xffffffffu, rs[mt][hf], 2);
        }
    __syncthreads();
    if (cq == 0) {
        #pragma unroll
        for (int mt = 0; mt < 2; mt++)
            #pragma unroll
            for (int hf = 0; hf < 2; hf++)
                s_rs[wq * 32 + mt * 16 + r + hf * 8][wn] = rs[mt][hf];
    }
    __syncthreads();
    if (tid < 64)
        s_inv[tid] = 1.f / (s_rs[tid][0] + s_rs[tid][1] + s_rs[tid][2] + s_rs[tid][3]);
    __syncthreads();

    float O[2][2][4];
    #pragma unroll
    for (int i=0;i<2;i++) for (int j=0;j<2;j++) for (int q=0;q<4;q++) O[i][j][q]=0.f;
    float inv_r[2][2];
    #pragma unroll
    for (int mt = 0; mt < 2; mt++)
        #pragma unroll
        for (int hf = 0; hf < 2; hf++)
            inv_r[mt][hf] = s_inv[wq * 32 + mt * 16 + r + hf * 8];

    // ---------------- pass 2: normalized attn + O ----------------
    for (int kt = 0; kt < 16; kt++) {
        const int k0g = kt * 128;
        __syncthreads();      // prev PV done reading P(=K space) and V
        #pragma unroll
        for (int i = tid; i < 2048; i += 256) {
            int t = i >> 10, e = i & 1023, rr = e >> 3, c8 = e & 7;
            const __nv_bfloat16* src = (t ? g_Kl : g_Kh) + ((size_t)bh * LL + k0g) * 64;
            cp16((t ? Kl : Kh) + rr * SQ + c8 * 8, src + (size_t)rr * 64 + c8 * 8);
        }
        #pragma unroll
        for (int i = tid; i < 2048; i += 256) {
            int t = i >> 10, e = i & 1023, rr = e >> 4, c8 = e & 15;
            const __nv_bfloat16* src = (t ? g_Vl : g_Vh) + (size_t)bh * 64 * LL;
            cp16((t ? Vl : Vh) + rr * SV + c8 * 8, src + (size_t)rr * LL + k0g + c8 * 8);
        }
        CP_COMMIT();
        if (tid < 128) s_msk[tid] = mask[b * LL + k0g + tid] ? 1.f : 0.f;
        asm volatile("cp.async.wait_group 0;" ::: "memory");
        __syncthreads();

        float Cs[2][4][4];
        #pragma unroll
        for (int i=0;i<2;i++) for (int j=0;j<4;j++) for (int q=0;q<4;q++) Cs[i][j][q]=0.f;
        #pragma unroll
        for (int ks = 0; ks < 4; ks++) {
            uint32_t fbh[4][2], fbl[4][2];
            #pragma unroll
            for (int nt = 0; nt < 4; nt++) {
                ldmB(fbh[nt], Kh, SQ, wn * 32 + nt * 8, ks * 16, lane);
                ldmB(fbl[nt], Kl, SQ, wn * 32 + nt * 8, ks * 16, lane);
            }
            #pragma unroll
            for (int mt = 0; mt < 2; mt++) {
                uint32_t fah[4], fal[4];
                ldmA(fah, Qh, SQ, wq * 32 + mt * 16, ks * 16, lane);
                ldmA(fal, Ql, SQ, wq * 32 + mt * 16, ks * 16, lane);
                #pragma unroll
                for (int nt = 0; nt < 4; nt++) {
                    mma16816(Cs[mt][nt], fah, fbh[nt]);
                    mma16816(Cs[mt][nt], fah, fbl[nt]);
                    mma16816(Cs[mt][nt], fal, fbh[nt]);
                }
            }
        }
        __syncthreads();      // ALL K reads done before P overwrites K space

        #pragma unroll
        for (int mt = 0; mt < 2; mt++) {
            #pragma unroll
            for (int nt = 0; nt < 4; nt++) {
                int col = wn * 32 + nt * 8 + 2 * cq;
                float m0 = s_msk[col], m1 = s_msk[col + 1];
                #pragma unroll
                for (int hf = 0; hf < 2; hf++) {
                    int row = wq * 32 + mt * 16 + r + hf * 8;
                    float iv = inv_r[mt][hf];
                    float e0 = fex2(Cs[mt][nt][hf*2+0]) * m0 * iv;
                    float e1 = fex2(Cs[mt][nt][hf*2+1]) * m1 * iv;
                    if (attn)
                        *(float2*)(attn + ((size_t)bh * LL + q0 + row) * LL + k0g + col) =
                            make_float2(e0, e1);
                    __nv_bfloat16 h0,l0,h1,l1; split_bf(e0,h0,l0); split_bf(e1,h1,l1);
                    *(__nv_bfloat162*)(Ph + (size_t)row * SV + col) = __halves2bfloat162(h0,h1);
                    *(__nv_bfloat162*)(Pl + (size_t)row * SV + col) = __halves2bfloat162(l0,l1);
                }
            }
        }
        __syncthreads();

        #pragma unroll
        for (int ks = 0; ks < 8; ks++) {
            uint32_t vbh[2][2], vbl[2][2];
            #pragma unroll
            for (int nt = 0; nt < 2; nt++) {
                ldmB(vbh[nt], Vh, SV, wn * 16 + nt * 8, ks * 16, lane);
                ldmB(vbl[nt], Vl, SV, wn * 16 + nt * 8, ks * 16, lane);
            }
            #pragma unroll
            for (int mt = 0; mt < 2; mt++) {
                uint32_t pah[4], pal[4];
                ldmA(pah, Ph, SV, wq * 32 + mt * 16, ks * 16, lane);
                ldmA(pal, Pl, SV, wq * 32 + mt * 16, ks * 16, lane);
                #pragma unroll
                for (int nt = 0; nt < 2; nt++) {
                    mma16816(O[mt][nt], pah, vbh[nt]);
                    mma16816(O[mt][nt], pah, vbl[nt]);
                    mma16816(O[mt][nt], pal, vbh[nt]);
                }
            }
        }
    }

    // ---- O epilogue (already normalized) ----
    #pragma unroll
    for (int mt = 0; mt < 2; mt++) {
        #pragma unroll
        for (int nt = 0; nt < 2; nt++) {
            int d = wn * 16 + nt * 8 + 2 * cq;
            #pragma unroll
            for (int hf = 0; hf < 2; hf++) {
                int row = wq * 32 + mt * 16 + r + hf * 8;
                __nv_bfloat16 h0,l0,h1,l1;
                split_bf(O[mt][nt][hf*2+0], h0, l0);
                split_bf(O[mt][nt][hf*2+1], h1, l1);
                size_t idx = ((size_t)b * LL + q0 + row) * DM + (bh & 15) * 64 + d;
                *(__nv_bfloat162*)(g_Oh + idx) = __halves2bfloat162(h0, h1);
                *(__nv_bfloat162*)(g_Ol + idx) = __halves2bfloat162(l0, l1);
            }
        }
    }
}

// ============================================================================
extern "C" void kernel_launch(void* const* d_in, const int* in_sizes, int n_in,
                              void* d_out, int out_size)
{
    const float* x    = (const float*)d_in[0];
    const int*   mask = (const int*)  d_in[1];
    const float* bq   = (const float*)d_in[3];
    const float* bk   = (const float*)d_in[5];
    const float* bv   = (const float*)d_in[7];
    const float* bo   = (const float*)d_in[9];
    float* out = (float*)d_out;

    const size_t out_elems  = (size_t)MM * DM;
    const size_t attn_elems = (size_t)BB * NH * LL * LL;
    float* attn = ((size_t)out_size >= out_elems + attn_elems) ? (out + out_elems) : nullptr;

    const int smem_proj = 2 * STG * 2;     // 81920 B
    const int smem_attn = 90112;
    cudaFuncSetAttribute(proj_kernel, cudaFuncAttributeMaxDynamicSharedMemorySize, smem_proj);
    cudaFuncSetAttribute(attn_kernel, cudaFuncAttributeMaxDynamicSharedMemorySize, smem_attn);

    const size_t total_cvt = (size_t)MM * DM + 4 * (size_t)DM * DM;
    cvt_all_kernel<<<(int)(total_cvt / 4 / 256), 256>>>(
        x, (const float*)d_in[2], (const float*)d_in[4],
        (const float*)d_in[6], (const float*)d_in[8]);

    proj_kernel<<<dim3(8, 32, 3), 256, smem_proj>>>(bq, bk, bv, nullptr, -1);

    attn_kernel<<<dim3(LL / 64, BB * NH), 256, smem_attn>>>(mask, attn);

    proj_kernel<<<dim3(8, 32, 1), 256, smem_proj>>>(bo, nullptr, nullptr, out, 3);
}

// round 9
// speedup vs baseline: 1.5476x; 1.5476x over previous
#include <cuda_runtime.h>
#include <cuda_fp16.h>
#include <cstdint>

#define BB 2
#define LL 2048
#define DM 1024
#define NH 16
#define MM (BB*LL)

// ---------------- device scratch (fp16) --------------------------------------
__device__ __align__(16) __half g_xh[MM*DM], g_xl[MM*DM];
__device__ __align__(16) __half g_w16[4][DM*DM];                 // hi only
__device__ __align__(16) __half g_Qh16[MM*DM], g_Ql16[MM*DM];    // [bh][l][64], scaled log2e/8
__device__ __align__(16) __half g_K16[MM*DM];                    // [bh][l][64]
__device__ __align__(16) __half g_V16[MM*DM];                    // transposed [bh][d][l]
__device__ __align__(16) __half g_Oh16[MM*DM], g_Ol16[MM*DM];    // [b][l][1024]

// ---------------- mma / ldmatrix / cp.async helpers -------------------------
__device__ __forceinline__ void mma16816(float* c, const uint32_t* a, const uint32_t* b){
    asm volatile("mma.sync.aligned.m16n8k16.row.col.f32.f16.f16.f32 "
        "{%0,%1,%2,%3}, {%4,%5,%6,%7}, {%8,%9}, {%0,%1,%2,%3};"
        : "+f"(c[0]), "+f"(c[1]), "+f"(c[2]), "+f"(c[3])
        : "r"(a[0]), "r"(a[1]), "r"(a[2]), "r"(a[3]), "r"(b[0]), "r"(b[1]));
}
__device__ __forceinline__ uint32_t smem_u32(const void* p){
    uint32_t a;
    asm("{ .reg .u64 t; cvta.to.shared.u64 t, %1; cvt.u32.u64 %0, t; }" : "=r"(a) : "l"(p));
    return a;
}
__device__ __forceinline__ void ldmA(uint32_t* a, const __half* s, int S, int m0, int k0, int lane){
    const __half* p = s + (size_t)(m0 + (lane & 15)) * S + k0 + ((lane >> 4) << 3);
    asm volatile("ldmatrix.sync.aligned.m8n8.x4.shared.b16 {%0,%1,%2,%3}, [%4];"
        : "=r"(a[0]), "=r"(a[1]), "=r"(a[2]), "=r"(a[3]) : "r"(smem_u32(p)));
}
__device__ __forceinline__ void ldmB(uint32_t* b, const __half* s, int S, int n0, int k0, int lane){
    const __half* p = s + (size_t)(n0 + (lane & 7)) * S + k0 + (((lane >> 3) & 1) << 3);
    asm volatile("ldmatrix.sync.aligned.m8n8.x2.shared.b16 {%0,%1}, [%2];"
        : "=r"(b[0]), "=r"(b[1]) : "r"(smem_u32(p)));
}
__device__ __forceinline__ void cp16(const __half* dst, const __half* src){
    asm volatile("cp.async.ca.shared.global [%0], [%1], 16;" :: "r"(smem_u32(dst)), "l"(src));
}
#define CP_COMMIT() asm volatile("cp.async.commit_group;" ::: "memory")
__device__ __forceinline__ void split_h(float v, __half& h, __half& l){
    h = __float2half_rn(v);
    l = __float2half_rn(v - __half2float(h));
}
__device__ __forceinline__ float fex2(float x){
    float y; asm("ex2.approx.f32 %0, %1;" : "=f"(y) : "f"(x)); return y;
}

// ============================================================================
// fp32 -> fp16 conversion: x hi/lo, weights hi only
// ============================================================================
__global__ __launch_bounds__(256) void cvt_all_kernel(
    const float* __restrict__ x,  const float* __restrict__ wq,
    const float* __restrict__ wk, const float* __restrict__ wv,
    const float* __restrict__ wo)
{
    size_t i4 = ((size_t)blockIdx.x * 256 + threadIdx.x) * 4;
    if (i4 < (size_t)MM * DM) {
        float4 v = *(const float4*)(x + i4);
        __half h0,l0,h1,l1,h2,l2,h3,l3;
        split_h(v.x,h0,l0); split_h(v.y,h1,l1); split_h(v.z,h2,l2); split_h(v.w,h3,l3);
        __half2 hh[2] = {__halves2half2(h0,h1), __halves2half2(h2,h3)};
        __half2 ll[2] = {__halves2half2(l0,l1), __halves2half2(l2,l3)};
        *(uint2*)(g_xh + i4) = *(uint2*)hh;
        *(uint2*)(g_xl + i4) = *(uint2*)ll;
    } else {
        size_t j = i4 - (size_t)MM * DM;
        int t = (int)(j >> 20);
        size_t off = j & ((1u << 20) - 1);
        const float* s = (t == 0) ? wq : (t == 1) ? wk : (t == 2) ? wv : wo;
        float4 v = *(const float4*)(s + off);
        __half2 hh[2] = {__halves2half2(__float2half_rn(v.x), __float2half_rn(v.y)),
                         __halves2half2(__float2half_rn(v.z), __float2half_rn(v.w))};
        *(uint2*)(g_w16[t] + off) = *(uint2*)hh;
    }
}

// ============================================================================
// projection GEMM: C = (Ah+Al) @ Bh^T + bias (2-term fp16), cp.async 2-stage.
// mode -1: blockIdx.z in {0:Q,1:K,2:V}; mode 3: out proj.
// ============================================================================
#define SA 40
#define STG (3*128*SA)     // 15360 halves per stage
__global__ __launch_bounds__(256, 2) void proj_kernel(
    const float* __restrict__ b0, const float* __restrict__ b1,
    const float* __restrict__ b2, float* __restrict__ fout, int mode_arg)
{
    extern __shared__ char smraw[];
    __half* S = (__half*)smraw;
    __shared__ float s_bias[128];

    const int mode = (mode_arg < 0) ? (int)blockIdx.z : mode_arg;
    const float* bias = (mode == 1) ? b1 : (mode == 2) ? b2 : b0;
    const __half* gAh = (mode < 3) ? g_xh : g_Oh16;
    const __half* gAl = (mode < 3) ? g_xl : g_Ol16;
    const __half* gBh = g_w16[mode];

    const int bm = blockIdx.y * 128, bn = blockIdx.x * 128;
    const int tid = threadIdx.x, w = tid >> 5, lane = tid & 31;
    const int wm = w >> 2, wn = w & 3;
    if (tid < 128) s_bias[tid] = bias[bn + tid];

    float C[4][4][4];
    #pragma unroll
    for (int i = 0; i < 4; i++)
        #pragma unroll
        for (int j = 0; j < 4; j++)
            #pragma unroll
            for (int q = 0; q < 4; q++) C[i][j][q] = 0.f;

    #pragma unroll
    for (int i = tid; i < 1536; i += 256) {
        int t = i >> 9, e = i & 511, r = e >> 2, c4 = e & 3;
        const __half* src = (t==0)?gAh:(t==1)?gAl:gBh;
        int rowbase = (t < 2) ? bm : bn;
        cp16(S + t * 5120 + r * SA + c4 * 8, src + (size_t)(rowbase + r) * DM + c4 * 8);
    }
    CP_COMMIT();

    for (int it = 0; it < 32; it++) {
        const int cur = it & 1;
        if (it + 1 < 32) {
            const int k0n = (it + 1) * 32, nxt = cur ^ 1;
            #pragma unroll
            for (int i = tid; i < 1536; i += 256) {
                int t = i >> 9, e = i & 511, r = e >> 2, c4 = e & 3;
                const __half* src = (t==0)?gAh:(t==1)?gAl:gBh;
                int rowbase = (t < 2) ? bm : bn;
                cp16(S + nxt * STG + t * 5120 + r * SA + c4 * 8,
                     src + (size_t)(rowbase + r) * DM + k0n + c4 * 8);
            }
            CP_COMMIT();
            asm volatile("cp.async.wait_group 1;" ::: "memory");
        } else {
            asm volatile("cp.async.wait_group 0;" ::: "memory");
        }
        __syncthreads();

        const __half *Ah = S + cur * STG, *Al = Ah + 5120, *Bh = Ah + 10240;
        #pragma unroll
        for (int ks = 0; ks < 2; ks++) {
            uint32_t fbh[4][2];
            #pragma unroll
            for (int nt = 0; nt < 4; nt++)
                ldmB(fbh[nt], Bh, SA, wn * 32 + nt * 8, ks * 16, lane);
            #pragma unroll
            for (int mt = 0; mt < 4; mt++) {
                uint32_t fah[4], fal[4];
                ldmA(fah, Ah, SA, wm * 64 + mt * 16, ks * 16, lane);
                ldmA(fal, Al, SA, wm * 64 + mt * 16, ks * 16, lane);
                #pragma unroll
                for (int nt = 0; nt < 4; nt++) {
                    mma16816(C[mt][nt], fah, fbh[nt]);
                    mma16816(C[mt][nt], fal, fbh[nt]);
                }
            }
        }
        __syncthreads();
    }

    const int r = lane >> 2, cq = lane & 3;
    const float scl = (mode == 0) ? 0.18033688011112042f : 1.0f;  // log2e/8
    #pragma unroll
    for (int mt = 0; mt < 4; mt++) {
        #pragma unroll
        for (int nt = 0; nt < 4; nt++) {
            int nloc = wn * 32 + nt * 8 + 2 * cq;
            int n = bn + nloc;
            #pragma unroll
            for (int hf = 0; hf < 2; hf++) {
                int m = bm + wm * 64 + mt * 16 + r + hf * 8;
                float v0 = (C[mt][nt][hf*2+0] + s_bias[nloc])     * scl;
                float v1 = (C[mt][nt][hf*2+1] + s_bias[nloc + 1]) * scl;
                if (mode == 3) {
                    *(float2*)(fout + (size_t)m * DM + n) = make_float2(v0, v1);
                } else {
                    int bidx = m >> 11, l = m & 2047, h = n >> 6, d = n & 63;
                    if (mode == 0) {
                        size_t idx = (((size_t)bidx * NH + h) * LL + l) * 64 + d;
                        __half h0,l0,h1,l1; split_h(v0,h0,l0); split_h(v1,h1,l1);
                        *(__half2*)(g_Qh16 + idx) = __halves2half2(h0, h1);
                        *(__half2*)(g_Ql16 + idx) = __halves2half2(l0, l1);
                    } else if (mode == 1) {
                        size_t idx = (((size_t)bidx * NH + h) * LL + l) * 64 + d;
                        *(__half2*)(g_K16 + idx) =
                            __halves2half2(__float2half_rn(v0), __float2half_rn(v1));
                    } else {
                        size_t idx = (((size_t)bidx * NH + h) * 64 + d) * LL + l;
                        g_V16[idx]      = __float2half_rn(v0);
                        g_V16[idx + LL] = __float2half_rn(v1);
                    }
                }
            }
        }
    }
}

// ============================================================================
// fused attention, TWO PASS, q-tile 64, fp16.
// pass1: S = Qh.K (1 MMA), K double-buffered (K0/K1), rowsums -> inv.
// pass2: S = (Qh+Ql).K (2 MMA) -> normalized attn + P fp16 (in K1 slot) ->
//        O += P.V (1 MMA).
// smem halves: Qh 0, Ql 4608, K0 9216, K1 18432 (P aliases K1), V 27648
// total 36352 halves = 72704 B
// ============================================================================
#define SQ 72
#define SV 136
__global__ __launch_bounds__(256, 2) void attn_kernel(const int* __restrict__ mask,
                                                      float* __restrict__ attn){
    extern __shared__ char smraw[];
    __half* S = (__half*)smraw;
    __half *Qh = S,          *Ql = S + 4608,
           *K0 = S + 9216,   *K1 = S + 18432,
           *Pt = S + 18432,  *Vt = S + 27648;
    __shared__ float s_msk[128];
    __shared__ float s_rs[64][4];
    __shared__ float s_inv[64];

    const int bh = blockIdx.y, q0 = blockIdx.x * 64, b = bh >> 4;
    const int tid = threadIdx.x, w = tid >> 5, lane = tid & 31;
    const int wq = w >> 2, wn = w & 3;
    const int r = lane >> 2, cq = lane & 3;

    // persistent Q tile [64][64] hi/lo
    #pragma unroll
    for (int i = tid; i < 1024; i += 256) {
        int t = i >> 9, e = i & 511, rr = e >> 3, c8 = e & 7;
        const __half* src = (t ? g_Ql16 : g_Qh16) + ((size_t)bh * LL + q0) * 64;
        cp16((t ? Ql : Qh) + rr * SQ + c8 * 8, src + (size_t)rr * 64 + c8 * 8);
    }
    // prefetch pass-1 K stage 0
    #pragma unroll
    for (int i = tid; i < 1024; i += 256) {
        int rr = i >> 3, c8 = i & 7;
        cp16(K0 + rr * SQ + c8 * 8,
             g_K16 + (size_t)bh * LL * 64 + (size_t)rr * 64 + c8 * 8);
    }
    CP_COMMIT();

    float rs[2][2] = {{0,0},{0,0}};

    // ---------------- pass 1: rowsums (Qh.K, double-buffered) --------------
    for (int kt = 0; kt < 16; kt++) {
        __syncthreads();
        const __half* Kcur = (kt & 1) ? K1 : K0;
        if (kt + 1 < 16) {
            __half* Knxt = (kt & 1) ? K0 : K1;
            const __half* src = g_K16 + ((size_t)bh * LL + (kt + 1) * 128) * 64;
            #pragma unroll
            for (int i = tid; i < 1024; i += 256) {
                int rr = i >> 3, c8 = i & 7;
                cp16(Knxt + rr * SQ + c8 * 8, src + (size_t)rr * 64 + c8 * 8);
            }
            CP_COMMIT();
            asm volatile("cp.async.wait_group 1;" ::: "memory");
        } else {
            asm volatile("cp.async.wait_group 0;" ::: "memory");
        }
        if (tid < 128) s_msk[tid] = mask[b * LL + kt * 128 + tid] ? 1.f : 0.f;
        __syncthreads();

        float Cs[2][4][4];
        #pragma unroll
        for (int i=0;i<2;i++) for (int j=0;j<4;j++) for (int q=0;q<4;q++) Cs[i][j][q]=0.f;
        #pragma unroll
        for (int ks = 0; ks < 4; ks++) {
            uint32_t fbh[4][2];
            #pragma unroll
            for (int nt = 0; nt < 4; nt++)
                ldmB(fbh[nt], Kcur, SQ, wn * 32 + nt * 8, ks * 16, lane);
            #pragma unroll
            for (int mt = 0; mt < 2; mt++) {
                uint32_t fah[4];
                ldmA(fah, Qh, SQ, wq * 32 + mt * 16, ks * 16, lane);
                #pragma unroll
                for (int nt = 0; nt < 4; nt++)
                    mma16816(Cs[mt][nt], fah, fbh[nt]);
            }
        }
        #pragma unroll
        for (int mt = 0; mt < 2; mt++)
            #pragma unroll
            for (int nt = 0; nt < 4; nt++) {
                int col = wn * 32 + nt * 8 + 2 * cq;
                float m0 = s_msk[col], m1 = s_msk[col + 1];
                #pragma unroll
                for (int hf = 0; hf < 2; hf++)
                    rs[mt][hf] += fex2(Cs[mt][nt][hf*2+0]) * m0
                                + fex2(Cs[mt][nt][hf*2+1]) * m1;
            }
    }

    #pragma unroll
    for (int mt = 0; mt < 2; mt++)
        #pragma unroll
        for (int hf = 0; hf < 2; hf++) {
            rs[mt][hf] += __shfl_xor_sync(0xffffffffu, rs[mt][hf], 1);
            rs[mt][hf] += __shfl_xor_sync(0xffffffffu, rs[mt][hf], 2);
        }
    __syncthreads();
    if (cq == 0) {
        #pragma unroll
        for (int mt = 0; mt < 2; mt++)
            #pragma unroll
            for (int hf = 0; hf < 2; hf++)
                s_rs[wq * 32 + mt * 16 + r + hf * 8][wn] = rs[mt][hf];
    }
    __syncthreads();
    if (tid < 64)
        s_inv[tid] = 1.f / (s_rs[tid][0] + s_rs[tid][1] + s_rs[tid][2] + s_rs[tid][3]);
    __syncthreads();

    float O[2][2][4];
    #pragma unroll
    for (int i=0;i<2;i++) for (int j=0;j<2;j++) for (int q=0;q<4;q++) O[i][j][q]=0.f;
    float inv_r[2][2];
    #pragma unroll
    for (int mt = 0; mt < 2; mt++)
        #pragma unroll
        for (int hf = 0; hf < 2; hf++)
            inv_r[mt][hf] = s_inv[wq * 32 + mt * 16 + r + hf * 8];

    // ---------------- pass 2: normalized attn + O ----------------
    for (int kt = 0; kt < 16; kt++) {
        const int k0g = kt * 128;
        __syncthreads();   // prev PV done reading P(K1) and V; K0 free
        #pragma unroll
        for (int i = tid; i < 1024; i += 256) {
            int rr = i >> 3, c8 = i & 7;
            const __half* src = g_K16 + ((size_t)bh * LL + k0g) * 64;
            cp16(K0 + rr * SQ + c8 * 8, src + (size_t)rr * 64 + c8 * 8);
        }
        #pragma unroll
        for (int i = tid; i < 1024; i += 256) {
            int rr = i >> 4, c8 = i & 15;
            const __half* src = g_V16 + (size_t)bh * 64 * LL;
            cp16(Vt + rr * SV + c8 * 8, src + (size_t)rr * LL + k0g + c8 * 8);
        }
        CP_COMMIT();
        if (tid < 128) s_msk[tid] = mask[b * LL + k0g + tid] ? 1.f : 0.f;
        asm volatile("cp.async.wait_group 0;" ::: "memory");
        __syncthreads();

        float Cs[2][4][4];
        #pragma unroll
        for (int i=0;i<2;i++) for (int j=0;j<4;j++) for (int q=0;q<4;q++) Cs[i][j][q]=0.f;
        #pragma unroll
        for (int ks = 0; ks < 4; ks++) {
            uint32_t fbh[4][2];
            #pragma unroll
            for (int nt = 0; nt < 4; nt++)
                ldmB(fbh[nt], K0, SQ, wn * 32 + nt * 8, ks * 16, lane);
            #pragma unroll
            for (int mt = 0; mt < 2; mt++) {
                uint32_t fah[4], fal[4];
                ldmA(fah, Qh, SQ, wq * 32 + mt * 16, ks * 16, lane);
                ldmA(fal, Ql, SQ, wq * 32 + mt * 16, ks * 16, lane);
                #pragma unroll
                for (int nt = 0; nt < 4; nt++) {
                    mma16816(Cs[mt][nt], fah, fbh[nt]);
                    mma16816(Cs[mt][nt], fal, fbh[nt]);
                }
            }
        }

        // P writes go to K1 slot (not K0) — safe alongside S reads of K0
        #pragma unroll
        for (int mt = 0; mt < 2; mt++) {
            #pragma unroll
            for (int nt = 0; nt < 4; nt++) {
                int col = wn * 32 + nt * 8 + 2 * cq;
                float m0 = s_msk[col], m1 = s_msk[col + 1];
                #pragma unroll
                for (int hf = 0; hf < 2; hf++) {
                    int row = wq * 32 + mt * 16 + r + hf * 8;
                    float iv = inv_r[mt][hf];
                    float e0 = fex2(Cs[mt][nt][hf*2+0]) * m0 * iv;
                    float e1 = fex2(Cs[mt][nt][hf*2+1]) * m1 * iv;
                    if (attn)
                        *(float2*)(attn + ((size_t)bh * LL + q0 + row) * LL + k0g + col) =
                            make_float2(e0, e1);
                    *(__half2*)(Pt + (size_t)row * SV + col) =
                        __halves2half2(__float2half_rn(e0), __float2half_rn(e1));
                }
            }
        }
        __syncthreads();

        #pragma unroll
        for (int ks = 0; ks < 8; ks++) {
            uint32_t vbh[2][2];
            #pragma unroll
            for (int nt = 0; nt < 2; nt++)
                ldmB(vbh[nt], Vt, SV, wn * 16 + nt * 8, ks * 16, lane);
            #pragma unroll
            for (int mt = 0; mt < 2; mt++) {
                uint32_t pah[4];
                ldmA(pah, Pt, SV, wq * 32 + mt * 16, ks * 16, lane);
                #pragma unroll
                for (int nt = 0; nt < 2; nt++)
                    mma16816(O[mt][nt], pah, vbh[nt]);
            }
        }
    }

    // ---- O epilogue (already normalized) ----
    #pragma unroll
    for (int mt = 0; mt < 2; mt++) {
        #pragma unroll
        for (int nt = 0; nt < 2; nt++) {
            int d = wn * 16 + nt * 8 + 2 * cq;
            #pragma unroll
            for (int hf = 0; hf < 2; hf++) {
                int row = wq * 32 + mt * 16 + r + hf * 8;
                __half h0,l0,h1,l1;
                split_h(O[mt][nt][hf*2+0], h0, l0);
                split_h(O[mt][nt][hf*2+1], h1, l1);
                size_t idx = ((size_t)b * LL + q0 + row) * DM + (bh & 15) * 64 + d;
                *(__half2*)(g_Oh16 + idx) = __halves2half2(h0, h1);
                *(__half2*)(g_Ol16 + idx) = __halves2half2(l0, l1);
            }
        }
    }
}

// ============================================================================
extern "C" void kernel_launch(void* const* d_in, const int* in_sizes, int n_in,
                              void* d_out, int out_size)
{
    const float* x    = (const float*)d_in[0];
    const int*   mask = (const int*)  d_in[1];
    const float* bq   = (const float*)d_in[3];
    const float* bk   = (const float*)d_in[5];
    const float* bv   = (const float*)d_in[7];
    const float* bo   = (const float*)d_in[9];
    float* out = (float*)d_out;

    const size_t out_elems  = (size_t)MM * DM;
    const size_t attn_elems = (size_t)BB * NH * LL * LL;
    float* attn = ((size_t)out_size >= out_elems + attn_elems) ? (out + out_elems) : nullptr;

    const int smem_proj = 2 * STG * 2;     // 61440 B
    const int smem_attn = 72704;
    cudaFuncSetAttribute(proj_kernel, cudaFuncAttributeMaxDynamicSharedMemorySize, smem_proj);
    cudaFuncSetAttribute(attn_kernel, cudaFuncAttributeMaxDynamicSharedMemorySize, smem_attn);

    const size_t total_cvt = (size_t)MM * DM + 4 * (size_t)DM * DM;
    cvt_all_kernel<<<(int)(total_cvt / 4 / 256), 256>>>(
        x, (const float*)d_in[2], (const float*)d_in[4],
        (const float*)d_in[6], (const float*)d_in[8]);

    proj_kernel<<<dim3(8, 32, 3), 256, smem_proj>>>(bq, bk, bv, nullptr, -1);

    attn_kernel<<<dim3(LL / 64, BB * NH), 256, smem_attn>>>(mask, attn);

    proj_kernel<<<dim3(8, 32, 1), 256, smem_proj>>>(bo, nullptr, nullptr, out, 3);
}